// round 6
// baseline (speedup 1.0000x reference)
#include <cuda_runtime.h>
#include <cstdint>

#define NB   32
#define H    1024
#define W    1024
#define BH   73
#define BW   73
#define BS   14                  // block stride = 16 - 3 + 1
#define NROWS (NB*BH)            // 2336 flag rows
#define TOTAL (NB*BH*BW)         // 170528
#define GRP  19                  // ceil(73/4) strip-groups per image

__device__ unsigned g_bits[NROWS * 3];   // 73-bit mask per row (slow path only)
__device__ int g_csum[NROWS];
__device__ int g_coff[NROWS];
__device__ int g_count;

// ---------------------------------------------------------------------------
// Kernel 1: fused pad + 16x16/stride14 max-pool + threshold.
// 128 threads / 4 warps per CTA; each CTA covers 4 strips (by rows) of one
// image. Load phase: 8 independent float4 loads per thread (MLP=8) into smem.
// Then warp w owns strip w: 73 windows in 3 ballot rounds over the probe row
// (row by*14). A window is decided-active unless all 16 probe samples <= 0.5
// (p = 2^-16); undecided strips take a warp-local full 16-row slow path.
// ---------------------------------------------------------------------------
__global__ __launch_bounds__(128) void pool_kernel(const float* __restrict__ mask) {
    const int cta = blockIdx.x;           // n*GRP + grp
    const int n   = cta / GRP;
    const int by0 = (cta % GRP) * 4;
    const int t    = threadIdx.x;
    const int warp = t >> 5, lane = t & 31;

    __shared__ float rows[4][W];

    const float4* base4 = (const float4*)(mask + (size_t)n * H * W);

    // ---- load 4 probe rows, front-batched for MLP ----
#pragma unroll
    for (int j = 0; j < 4; j++) {
        int by = by0 + j;
        if (by < BH) {
            const float4* src = base4 + (size_t)(by * BS) * (W / 4);
            float4 a = src[t];
            float4 b = src[t + 128];
            ((float4*)rows[j])[t]       = a;
            ((float4*)rows[j])[t + 128] = b;
        }
    }
    __syncthreads();

    const int by = by0 + warp;
    if (by >= BH) return;
    const int row = n * BH + by;
    float* cm = rows[warp];

    // ---- probe-row window max, 3 ballot rounds ----
    unsigned bits[3];
#pragma unroll
    for (int i = 0; i < 3; i++) {
        int wi = i * 32 + lane;
        int flag = 0;
        if (wi < BW) {
            float mx = 0.f;
            int c0 = wi * BS - 1;
#pragma unroll
            for (int k = 0; k < 16; k++) {
                int c = c0 + k;
                if (c >= 0 && c < W) mx = fmaxf(mx, cm[c]);
            }
            flag = (mx > 0.5f) ? 1 : 0;
        }
        bits[i] = __ballot_sync(0xffffffffu, flag);
    }
    int cnt = __popc(bits[0]) + __popc(bits[1]) + __popc(bits[2]);

    if (cnt == BW) {                      // fast path: every window active
        if (lane == 0) g_csum[row] = BW;
        return;
    }

    // ---- warp-local slow path: full 16-row colmax, then re-evaluate ----
    const int row0 = by * BS - 1;         // may be -1 (zero pad); row0+15 <= 1022
#pragma unroll
    for (int ch = 0; ch < 8; ch++) {      // 8 chunks x 32 lanes x float4 = 1024 cols
        float4 m = make_float4(0.f, 0.f, 0.f, 0.f);
        for (int r = 0; r < 16; r++) {
            int real = row0 + r;
            if (real < 0) continue;
            float4 u = base4[(size_t)real * (W / 4) + ch * 32 + lane];
            m.x = fmaxf(m.x, u.x); m.y = fmaxf(m.y, u.y);
            m.z = fmaxf(m.z, u.z); m.w = fmaxf(m.w, u.w);
        }
        __syncwarp();                     // probe-phase reads of cm are done
        ((float4*)cm)[ch * 32 + lane] = m;
    }
    __syncwarp();

#pragma unroll
    for (int i = 0; i < 3; i++) {
        int wi = i * 32 + lane;
        int flag = 0;
        if (wi < BW) {
            float mx = 0.f;
            int c0 = wi * BS - 1;
#pragma unroll
            for (int k = 0; k < 16; k++) {
                int c = c0 + k;
                if (c >= 0 && c < W) mx = fmaxf(mx, cm[c]);
            }
            flag = (mx > 0.5f) ? 1 : 0;
        }
        bits[i] = __ballot_sync(0xffffffffu, flag);
    }
    if (lane == 0) {
        g_bits[row * 3 + 0] = bits[0];
        g_bits[row * 3 + 1] = bits[1];
        g_bits[row * 3 + 2] = bits[2];
        g_csum[row] = __popc(bits[0]) + __popc(bits[1]) + __popc(bits[2]);
    }
}

// ---------------------------------------------------------------------------
// Kernel 2: parallel exclusive scan of 2336 row sums (1 CTA, 256 threads).
// ---------------------------------------------------------------------------
#define PER 10   // 256*10 = 2560 >= 2336

__global__ __launch_bounds__(256) void scan_kernel(float* __restrict__ out,
                                                   int count_idx) {
    const int t = threadIdx.x;
    const int lane = t & 31, w = t >> 5;
    __shared__ int wtot[8];
    __shared__ int woff[8];

    int local[PER];
    int s = 0;
    int base = t * PER;
#pragma unroll
    for (int i = 0; i < PER; i++) {
        int g = base + i;
        local[i] = (g < NROWS) ? g_csum[g] : 0;
        s += local[i];
    }

    int x = s;                            // warp inclusive scan
#pragma unroll
    for (int off = 1; off < 32; off <<= 1) {
        int y = __shfl_up_sync(0xffffffffu, x, off);
        if (lane >= off) x += y;
    }
    if (lane == 31) wtot[w] = x;
    __syncthreads();
    if (t == 0) {
        int acc = 0;
        for (int i = 0; i < 8; i++) { woff[i] = acc; acc += wtot[i]; }
        g_count = acc;
        if (count_idx >= 0) out[count_idx] = (float)acc;
    }
    __syncthreads();

    int excl = woff[w] + x - s;
#pragma unroll
    for (int i = 0; i < PER; i++) {
        int g = base + i;
        if (g < NROWS) g_coff[g] = excl;
        excl += local[i];
    }
}

// ---------------------------------------------------------------------------
// Kernel 3: scatter. One CTA (96 thr) per row. Fast rows (csum==73) write
// their 73 active triples directly. Slow rows use the bitmask + popc prefix;
// inactive elements write the fill triple at count + inactive_rank (inactive
// ranks are globally contiguous), so no tail-fill pass is needed.
// ---------------------------------------------------------------------------
__global__ __launch_bounds__(96) void scatter_kernel(float* __restrict__ out) {
    const int row = blockIdx.x;          // n*BH + by
    const int t = threadIdx.x;
    if (t >= BW) return;

    const int cnt = g_csum[row];
    const int off = g_coff[row];
    const int i0 = row / BH;
    const int i1 = row - i0 * BH;

    if (cnt == BW) {                     // fast path: all 73 active
        int pos = off + t;
        out[3 * pos + 0] = (float)i0;
        out[3 * pos + 1] = (float)i1;
        out[3 * pos + 2] = (float)t;
        return;
    }

    unsigned w0 = g_bits[row * 3 + 0];
    unsigned w1 = g_bits[row * 3 + 1];
    unsigned w2 = g_bits[row * 3 + 2];
    unsigned lmask = (1u << (t & 31)) - 1u;

    int below, f;
    if (t < 32)      { below = __popc(w0 & lmask);                           f = (w0 >> t) & 1; }
    else if (t < 64) { below = __popc(w0) + __popc(w1 & lmask);              f = (w1 >> (t - 32)) & 1; }
    else             { below = __popc(w0) + __popc(w1) + __popc(w2 & lmask); f = (w2 >> (t - 64)) & 1; }

    if (f) {
        int pos = off + below;
        out[3 * pos + 0] = (float)i0;
        out[3 * pos + 1] = (float)i1;
        out[3 * pos + 2] = (float)t;
    } else {
        int g = row * BW + t;
        int pos = g_count + (g - (off + below));   // contiguous inactive ranks
        out[3 * pos + 0] = (float)NB;
        out[3 * pos + 1] = (float)BH;
        out[3 * pos + 2] = (float)BW;
    }
}

extern "C" void kernel_launch(void* const* d_in, const int* in_sizes, int n_in,
                              void* d_out, int out_size) {
    const float* mask = (const float*)d_in[0];
    float* out = (float*)d_out;

    int count_idx = (out_size > 3 * TOTAL) ? (out_size - 1) : -1;

    pool_kernel<<<NB * GRP, 128>>>(mask);
    scan_kernel<<<1, 256>>>(out, count_idx);
    scatter_kernel<<<NROWS, 96>>>(out);
}

// round 7
// speedup vs baseline: 1.0133x; 1.0133x over previous
#include <cuda_runtime.h>
#include <cstdint>

#define NB   32
#define H    1024
#define W    1024
#define BH   73
#define BW   73
#define BS   14                  // block stride = 16 - 3 + 1
#define NROWS (NB*BH)            // 2336 flag rows
#define TOTAL (NB*BH*BW)         // 170528
#define GRP  19                  // ceil(73/4) strip-groups per image

__device__ unsigned g_bits[NROWS * 3];   // 73-bit mask per row (slow path only)
__device__ int g_csum[NROWS];
__device__ int g_coff[NROWS];
__device__ int g_count;

// ---------------------------------------------------------------------------
// Kernel 1: fused pad + 16x16/stride14 max-pool + threshold.
// 128 threads / 4 warps per CTA; warp w owns strip by0+w. Each warp pulls its
// probe row (by*14, 4KB) into smem with 8x cp.async 16B per lane — full MLP
// with zero register pressure — then waits on ITS OWN copies only
// (wait_group + syncwarp; no CTA barrier). A window is decided-active unless
// all 16 probe samples <= 0.5 (p = 2^-16); undecided strips take a
// warp-local full 16-row slow path (~3 strips per launch).
// ---------------------------------------------------------------------------
__global__ __launch_bounds__(128) void pool_kernel(const float* __restrict__ mask) {
    const int cta = blockIdx.x;           // n*GRP + grp
    const int n   = cta / GRP;
    const int by0 = (cta % GRP) * 4;
    const int t    = threadIdx.x;
    const int warp = t >> 5, lane = t & 31;

    __shared__ float rows[4][W];          // 16KB

    const float4* base4 = (const float4*)(mask + (size_t)n * H * W);
    const int by = by0 + warp;

    // ---- async load: this warp's probe row, 8 chunks x 16B per lane ----
    if (by < BH) {
        const float4* src = base4 + (size_t)(by * BS) * (W / 4);
        float4* dst = (float4*)rows[warp];
#pragma unroll
        for (int ch = 0; ch < 8; ch++) {
            unsigned sa = (unsigned)__cvta_generic_to_shared(&dst[ch * 32 + lane]);
            const float4* gp = &src[ch * 32 + lane];
            asm volatile("cp.async.cg.shared.global [%0], [%1], 16;"
                         :: "r"(sa), "l"(gp) : "memory");
        }
    }
    asm volatile("cp.async.commit_group;" ::: "memory");
    asm volatile("cp.async.wait_group 0;" ::: "memory");
    __syncwarp();

    if (by >= BH) return;
    const int row = n * BH + by;
    float* cm = rows[warp];

    // ---- probe-row window max, 3 ballot rounds ----
    unsigned bits[3];
#pragma unroll
    for (int i = 0; i < 3; i++) {
        int wi = i * 32 + lane;
        int flag = 0;
        if (wi < BW) {
            float mx = 0.f;
            int c0 = wi * BS - 1;
#pragma unroll
            for (int k = 0; k < 16; k++) {
                int c = c0 + k;
                if (c >= 0 && c < W) mx = fmaxf(mx, cm[c]);
            }
            flag = (mx > 0.5f) ? 1 : 0;
        }
        bits[i] = __ballot_sync(0xffffffffu, flag);
    }
    int cnt = __popc(bits[0]) + __popc(bits[1]) + __popc(bits[2]);

    if (cnt == BW) {                      // fast path: every window active
        if (lane == 0) g_csum[row] = BW;
        return;
    }

    // ---- warp-local slow path: full 16-row colmax, then re-evaluate ----
    const int row0 = by * BS - 1;         // may be -1 (zero pad); row0+15 <= 1022
#pragma unroll
    for (int ch = 0; ch < 8; ch++) {      // 8 chunks x 32 lanes x float4 = 1024 cols
        float4 m = make_float4(0.f, 0.f, 0.f, 0.f);
        for (int r = 0; r < 16; r++) {
            int real = row0 + r;
            if (real < 0) continue;
            float4 u = base4[(size_t)real * (W / 4) + ch * 32 + lane];
            m.x = fmaxf(m.x, u.x); m.y = fmaxf(m.y, u.y);
            m.z = fmaxf(m.z, u.z); m.w = fmaxf(m.w, u.w);
        }
        __syncwarp();                     // probe-phase reads of cm are done
        ((float4*)cm)[ch * 32 + lane] = m;
    }
    __syncwarp();

#pragma unroll
    for (int i = 0; i < 3; i++) {
        int wi = i * 32 + lane;
        int flag = 0;
        if (wi < BW) {
            float mx = 0.f;
            int c0 = wi * BS - 1;
#pragma unroll
            for (int k = 0; k < 16; k++) {
                int c = c0 + k;
                if (c >= 0 && c < W) mx = fmaxf(mx, cm[c]);
            }
            flag = (mx > 0.5f) ? 1 : 0;
        }
        bits[i] = __ballot_sync(0xffffffffu, flag);
    }
    if (lane == 0) {
        g_bits[row * 3 + 0] = bits[0];
        g_bits[row * 3 + 1] = bits[1];
        g_bits[row * 3 + 2] = bits[2];
        g_csum[row] = __popc(bits[0]) + __popc(bits[1]) + __popc(bits[2]);
    }
}

// ---------------------------------------------------------------------------
// Kernel 2: parallel exclusive scan of 2336 row sums (1 CTA, 256 threads).
// ---------------------------------------------------------------------------
#define PER 10   // 256*10 = 2560 >= 2336

__global__ __launch_bounds__(256) void scan_kernel(float* __restrict__ out,
                                                   int count_idx) {
    const int t = threadIdx.x;
    const int lane = t & 31, w = t >> 5;
    __shared__ int wtot[8];
    __shared__ int woff[8];

    int local[PER];
    int s = 0;
    int base = t * PER;
#pragma unroll
    for (int i = 0; i < PER; i++) {
        int g = base + i;
        local[i] = (g < NROWS) ? g_csum[g] : 0;
        s += local[i];
    }

    int x = s;                            // warp inclusive scan
#pragma unroll
    for (int off = 1; off < 32; off <<= 1) {
        int y = __shfl_up_sync(0xffffffffu, x, off);
        if (lane >= off) x += y;
    }
    if (lane == 31) wtot[w] = x;
    __syncthreads();
    if (t == 0) {
        int acc = 0;
        for (int i = 0; i < 8; i++) { woff[i] = acc; acc += wtot[i]; }
        g_count = acc;
        if (count_idx >= 0) out[count_idx] = (float)acc;
    }
    __syncthreads();

    int excl = woff[w] + x - s;
#pragma unroll
    for (int i = 0; i < PER; i++) {
        int g = base + i;
        if (g < NROWS) g_coff[g] = excl;
        excl += local[i];
    }
}

// ---------------------------------------------------------------------------
// Kernel 3: scatter. One CTA (96 thr) per row. Fast rows (csum==73) write
// their 73 active triples directly. Slow rows use the bitmask + popc prefix;
// inactive elements write the fill triple at count + inactive_rank (inactive
// ranks are globally contiguous), so no tail-fill pass is needed.
// ---------------------------------------------------------------------------
__global__ __launch_bounds__(96) void scatter_kernel(float* __restrict__ out) {
    const int row = blockIdx.x;          // n*BH + by
    const int t = threadIdx.x;
    if (t >= BW) return;

    const int cnt = g_csum[row];
    const int off = g_coff[row];
    const int i0 = row / BH;
    const int i1 = row - i0 * BH;

    if (cnt == BW) {                     // fast path: all 73 active
        int pos = off + t;
        out[3 * pos + 0] = (float)i0;
        out[3 * pos + 1] = (float)i1;
        out[3 * pos + 2] = (float)t;
        return;
    }

    unsigned w0 = g_bits[row * 3 + 0];
    unsigned w1 = g_bits[row * 3 + 1];
    unsigned w2 = g_bits[row * 3 + 2];
    unsigned lmask = (1u << (t & 31)) - 1u;

    int below, f;
    if (t < 32)      { below = __popc(w0 & lmask);                           f = (w0 >> t) & 1; }
    else if (t < 64) { below = __popc(w0) + __popc(w1 & lmask);              f = (w1 >> (t - 32)) & 1; }
    else             { below = __popc(w0) + __popc(w1) + __popc(w2 & lmask); f = (w2 >> (t - 64)) & 1; }

    if (f) {
        int pos = off + below;
        out[3 * pos + 0] = (float)i0;
        out[3 * pos + 1] = (float)i1;
        out[3 * pos + 2] = (float)t;
    } else {
        int g = row * BW + t;
        int pos = g_count + (g - (off + below));   // contiguous inactive ranks
        out[3 * pos + 0] = (float)NB;
        out[3 * pos + 1] = (float)BH;
        out[3 * pos + 2] = (float)BW;
    }
}

extern "C" void kernel_launch(void* const* d_in, const int* in_sizes, int n_in,
                              void* d_out, int out_size) {
    const float* mask = (const float*)d_in[0];
    float* out = (float*)d_out;

    int count_idx = (out_size > 3 * TOTAL) ? (out_size - 1) : -1;

    pool_kernel<<<NB * GRP, 128>>>(mask);
    scan_kernel<<<1, 256>>>(out, count_idx);
    scatter_kernel<<<NROWS, 96>>>(out);
}